// round 1
// baseline (speedup 1.0000x reference)
#include <cuda_runtime.h>
#include <cstdint>

// Problem constants (shapes fixed by the reference)
#define IN_F      256
#define OUT_F     256
#define OUTSTRIDE 512   // output row = [ft_input(256) | ft_neighbor(256)]

// ---------------------------------------------------------------------------
// Index-width detection: reference declares int64 edge indices, but JAX
// without x64 silently gives int32. Detect once per launch (deterministic):
// if data is int64, every odd 32-bit word is 0 (values in [0,100000));
// if int32, odd words are random node ids (nonzero a.s. over 256 samples).
// ---------------------------------------------------------------------------
__device__ unsigned g_idx_is64;

__global__ void detect_idx_kernel(const unsigned* __restrict__ p) {
    unsigned v = p[2 * threadIdx.x + 1];        // 256 odd-position words
    int any = __syncthreads_or(v != 0u);
    if (threadIdx.x == 0) g_idx_is64 = any ? 0u : 1u;
}

// ---------------------------------------------------------------------------
// Zero the ft_neighbor half of the output (cols [256,512) of each row).
// ---------------------------------------------------------------------------
__global__ void zero_neighbor_kernel(float* __restrict__ out, int M) {
    int idx = blockIdx.x * blockDim.x + threadIdx.x;   // one float4 each
    int total = M * (OUT_F / 4);                        // M * 64
    if (idx < total) {
        int row = idx >> 6;
        int c4  = idx & 63;
        reinterpret_cast<float4*>(out + (size_t)row * OUTSTRIDE + OUT_F)[c4] =
            make_float4(0.f, 0.f, 0.f, 0.f);
    }
}

// ---------------------------------------------------------------------------
// fp32 tiled GEMM: out[:, bn:bn+128] = input[M,256] @ W[256,256] (exact fp32)
// BM=128, BN=128, BK=16, 256 threads, 8x8 per thread.
// ---------------------------------------------------------------------------
#define BM 128
#define BN 128
#define BK 16
#define TM 8
#define TN 8

__global__ __launch_bounds__(256, 2)
void gemm_kernel(const float* __restrict__ A,   // [M, 256]
                 const float* __restrict__ W,   // [256, 256]
                 float* __restrict__ out,       // [M, 512]
                 int M) {
    __shared__ float As[BK][BM];
    __shared__ float Bs[BK][BN];

    const int tid = threadIdx.x;
    const int bm  = blockIdx.x * BM;
    const int bn  = blockIdx.y * BN;

    const int tx = tid & 15;   // N-tile index (16)
    const int ty = tid >> 4;   // M-tile index (16)

    float acc[TM][TN];
#pragma unroll
    for (int i = 0; i < TM; i++)
#pragma unroll
        for (int j = 0; j < TN; j++) acc[i][j] = 0.f;

    // A-tile load mapping: 128 rows x 16 cols -> 512 float4, 2 per thread
    const int a_r = tid >> 2;          // 0..63
    const int a_c = (tid & 3) * 4;     // 0,4,8,12
    // B-tile load mapping: 16 rows x 128 cols -> 512 float4, 2 per thread
    const int b_r = tid >> 5;          // 0..7
    const int b_c = (tid & 31) * 4;    // 0..124

    for (int k0 = 0; k0 < IN_F; k0 += BK) {
#pragma unroll
        for (int s = 0; s < 2; s++) {
            int row  = a_r + s * 64;
            int grow = bm + row;
            float4 v = make_float4(0.f, 0.f, 0.f, 0.f);
            if (grow < M)
                v = *reinterpret_cast<const float4*>(A + (size_t)grow * IN_F + k0 + a_c);
            As[a_c + 0][row] = v.x;
            As[a_c + 1][row] = v.y;
            As[a_c + 2][row] = v.z;
            As[a_c + 3][row] = v.w;
        }
#pragma unroll
        for (int s = 0; s < 2; s++) {
            int row = b_r + s * 8;
            float4 v = *reinterpret_cast<const float4*>(
                W + (size_t)(k0 + row) * OUT_F + bn + b_c);
            *reinterpret_cast<float4*>(&Bs[row][b_c]) = v;
        }
        __syncthreads();

#pragma unroll
        for (int k = 0; k < BK; k++) {
            float ra[TM], rb[TN];
            float4 a0 = *reinterpret_cast<const float4*>(&As[k][ty * TM]);
            float4 a1 = *reinterpret_cast<const float4*>(&As[k][ty * TM + 4]);
            ra[0]=a0.x; ra[1]=a0.y; ra[2]=a0.z; ra[3]=a0.w;
            ra[4]=a1.x; ra[5]=a1.y; ra[6]=a1.z; ra[7]=a1.w;
            float4 b0 = *reinterpret_cast<const float4*>(&Bs[k][tx * TN]);
            float4 b1 = *reinterpret_cast<const float4*>(&Bs[k][tx * TN + 4]);
            rb[0]=b0.x; rb[1]=b0.y; rb[2]=b0.z; rb[3]=b0.w;
            rb[4]=b1.x; rb[5]=b1.y; rb[6]=b1.z; rb[7]=b1.w;
#pragma unroll
            for (int i = 0; i < TM; i++)
#pragma unroll
                for (int j = 0; j < TN; j++)
                    acc[i][j] += ra[i] * rb[j];
        }
        __syncthreads();
    }

#pragma unroll
    for (int i = 0; i < TM; i++) {
        int grow = bm + ty * TM + i;
        if (grow < M) {
            float* orow = out + (size_t)grow * OUTSTRIDE + bn + tx * TN;
            *reinterpret_cast<float4*>(orow)     = make_float4(acc[i][0], acc[i][1], acc[i][2], acc[i][3]);
            *reinterpret_cast<float4*>(orow + 4) = make_float4(acc[i][4], acc[i][5], acc[i][6], acc[i][7]);
        }
    }
}

// ---------------------------------------------------------------------------
// Edge scatter: out[dst, 256+c] += val * out[src, c], one warp per edge,
// 128 features per pass (lane -> one float4). Two passes keep the per-pass
// working set (~102 MB) inside L2.
// ---------------------------------------------------------------------------
__global__ __launch_bounds__(256)
void scatter_kernel(const void* __restrict__ esrc_raw,
                    const void* __restrict__ edst_raw,
                    const float* __restrict__ eval,
                    float* out, int E, int colOff) {
    const unsigned is64 = g_idx_is64;
    const int lane    = threadIdx.x & 31;
    const int warpId  = (blockIdx.x * blockDim.x + threadIdx.x) >> 5;
    const int nWarps  = (gridDim.x * blockDim.x) >> 5;

    const long long* src64 = reinterpret_cast<const long long*>(esrc_raw);
    const long long* dst64 = reinterpret_cast<const long long*>(edst_raw);
    const int*       src32 = reinterpret_cast<const int*>(esrc_raw);
    const int*       dst32 = reinterpret_cast<const int*>(edst_raw);

    for (int e = warpId; e < E; e += nWarps) {
        long long s, d;
        if (is64) { s = __ldg(src64 + e); d = __ldg(dst64 + e); }
        else      { s = __ldg(src32 + e); d = __ldg(dst32 + e); }
        float v = __ldg(eval + e);

        const float4* srcp =
            reinterpret_cast<const float4*>(out + (size_t)s * OUTSTRIDE + colOff);
        float4 g = __ldg(srcp + lane);

        float4 r = make_float4(g.x * v, g.y * v, g.z * v, g.w * v);
        float* dstp = out + (size_t)d * OUTSTRIDE + OUT_F + colOff + lane * 4;
        asm volatile("red.global.add.v4.f32 [%0], {%1,%2,%3,%4};"
                     :: "l"(dstp), "f"(r.x), "f"(r.y), "f"(r.z), "f"(r.w)
                     : "memory");
    }
}

// ---------------------------------------------------------------------------
// Launch
// ---------------------------------------------------------------------------
extern "C" void kernel_launch(void* const* d_in, const int* in_sizes, int n_in,
                              void* d_out, int out_size) {
    const float* input  = (const float*)d_in[0];   // [N, 256]
    const void*  esrc   = d_in[1];                 // [E] int32 or int64
    const void*  edst   = d_in[2];                 // [E]
    const float* evals  = (const float*)d_in[3];   // [E]
    const float* weight = (const float*)d_in[4];   // [256, 256]
    float* out = (float*)d_out;                    // [N, 512]

    const int M = in_sizes[0] / IN_F;              // 100000
    const int E = in_sizes[1];                     // 3200000

    detect_idx_kernel<<<1, 256>>>((const unsigned*)esrc);

    int zt = M * (OUT_F / 4);
    zero_neighbor_kernel<<<(zt + 255) / 256, 256>>>(out, M);

    dim3 gg((M + BM - 1) / BM, OUT_F / BN);        // (782, 2)
    gemm_kernel<<<gg, 256>>>(input, weight, out, M);

    // Two feature-sliced passes so each pass's gather+atomic set fits in L2.
    scatter_kernel<<<1184, 256>>>(esrc, edst, evals, out, E, 0);
    scatter_kernel<<<1184, 256>>>(esrc, edst, evals, out, E, 128);
}

// round 3
// speedup vs baseline: 1.1700x; 1.1700x over previous
#include <cuda_runtime.h>
#include <cuda_bf16.h>
#include <cstdint>

#define IN_F      256
#define OUT_F     256
#define OUTSTRIDE 512
#define MAXE      3200000

// ---------------- device scratch (allocation-free rule) ---------------------
__device__ __nv_bfloat16 g_Whi[OUT_F * IN_F];   // transposed: [n][k]
__device__ __nv_bfloat16 g_Wlo[OUT_F * IN_F];
__device__ int4          g_edges[MAXE];         // {src, dst, val_bits, pad}
__device__ unsigned      g_idx_is64;

// ---------------- helpers ---------------------------------------------------
static __device__ __forceinline__ uint32_t smem_u32(const void* p) {
    uint32_t a;
    asm("{ .reg .u64 t; cvta.to.shared.u64 t, %1; cvt.u32.u64 %0, t; }"
        : "=r"(a) : "l"(p));
    return a;
}
static __device__ __forceinline__ void ldsm4(uint32_t* r, uint32_t addr) {
    asm volatile("ldmatrix.sync.aligned.m8n8.x4.shared.b16 {%0,%1,%2,%3}, [%4];"
                 : "=r"(r[0]), "=r"(r[1]), "=r"(r[2]), "=r"(r[3]) : "r"(addr));
}
static __device__ __forceinline__ void mma16816(float* c, const uint32_t* a,
                                                const uint32_t* b) {
    asm volatile(
        "mma.sync.aligned.m16n8k16.row.col.f32.bf16.bf16.f32 "
        "{%0,%1,%2,%3}, {%4,%5,%6,%7}, {%8,%9}, {%0,%1,%2,%3};"
        : "+f"(c[0]), "+f"(c[1]), "+f"(c[2]), "+f"(c[3])
        : "r"(a[0]), "r"(a[1]), "r"(a[2]), "r"(a[3]), "r"(b[0]), "r"(b[1]));
}
static __device__ __forceinline__ uint32_t pack2(__nv_bfloat16 a, __nv_bfloat16 b) {
    return ((uint32_t)__bfloat16_as_ushort(b) << 16) | __bfloat16_as_ushort(a);
}

// ---------------------------------------------------------------------------
// Index-width detection (int64 vs int32 edge indices).
// ---------------------------------------------------------------------------
__global__ void detect_idx_kernel(const unsigned* __restrict__ p) {
    unsigned v = p[2 * threadIdx.x + 1];
    int any = __syncthreads_or(v != 0u);
    if (threadIdx.x == 0) g_idx_is64 = any ? 0u : 1u;
}

// ---------------------------------------------------------------------------
// Zero the ft_neighbor half of the output.
// ---------------------------------------------------------------------------
__global__ void zero_neighbor_kernel(float* __restrict__ out, int M) {
    int idx = blockIdx.x * blockDim.x + threadIdx.x;
    int total = M * (OUT_F / 4);
    if (idx < total) {
        int row = idx >> 6;
        int c4  = idx & 63;
        reinterpret_cast<float4*>(out + (size_t)row * OUTSTRIDE + OUT_F)[c4] =
            make_float4(0.f, 0.f, 0.f, 0.f);
    }
}

// ---------------------------------------------------------------------------
// W[k][n] -> transposed bf16 hi/lo: g_W{hi,lo}[n][k].
// ---------------------------------------------------------------------------
__global__ void conv_w_kernel(const float* __restrict__ W) {
    int i = blockIdx.x * blockDim.x + threadIdx.x;   // 65536
    int k = i >> 8, n = i & 255;
    float x = W[i];
    __nv_bfloat16 h = __float2bfloat16_rn(x);
    g_Whi[n * IN_F + k] = h;
    g_Wlo[n * IN_F + k] = __float2bfloat16_rn(x - __bfloat162float(h));
}

// ---------------------------------------------------------------------------
// Pack edges into 16B records {src, dst, val, 0}.
// ---------------------------------------------------------------------------
__global__ void pack_edges_kernel(const void* __restrict__ esrc,
                                  const void* __restrict__ edst,
                                  const float* __restrict__ ev, int E) {
    int i = blockIdx.x * blockDim.x + threadIdx.x;
    if (i >= E) return;
    int s, d;
    if (g_idx_is64) {
        s = (int)__ldg((const long long*)esrc + i);
        d = (int)__ldg((const long long*)edst + i);
    } else {
        s = __ldg((const int*)esrc + i);
        d = __ldg((const int*)edst + i);
    }
    g_edges[i] = make_int4(s, d, __float_as_int(__ldg(ev + i)), 0);
}

// ---------------------------------------------------------------------------
// GEMM via mma.sync (HMMA.16816 bf16), split-bf16 3-product for fp32 accuracy.
// Block 128x128, 8 warps (warp tile 32x64), K-chunk 32, K=256.
// A (fp32 X) converted to hi/lo bf16 in the smem-fill stage.
// Smem stride 40 bf16 (80B): ldmatrix rows hit distinct banks (r*20 mod 32).
// ---------------------------------------------------------------------------
#define SSTR 40

__global__ __launch_bounds__(256)
void gemm_mma_kernel(const float* __restrict__ X, float* __restrict__ out, int M) {
    __shared__ __align__(16) __nv_bfloat16 sAhi[128 * SSTR];
    __shared__ __align__(16) __nv_bfloat16 sAlo[128 * SSTR];
    __shared__ __align__(16) __nv_bfloat16 sBhi[128 * SSTR];
    __shared__ __align__(16) __nv_bfloat16 sBlo[128 * SSTR];

    const int tid  = threadIdx.x;
    const int lane = tid & 31, wid = tid >> 5;
    const int bm = blockIdx.x * 128;
    const int bn = blockIdx.y * 128;
    const int wm = (wid & 3) * 32;     // 4 warps along M
    const int wn = (wid >> 2) * 64;    // 2 warps along N

    float acc[2][8][4];
#pragma unroll
    for (int i = 0; i < 2; i++)
#pragma unroll
        for (int j = 0; j < 8; j++)
#pragma unroll
            for (int k = 0; k < 4; k++) acc[i][j][k] = 0.f;

    // ldmatrix per-lane row/col offsets
    // A x4: mats (m0k0),(m8k0),(m0k8),(m8k8)
    const int rA = ((lane >> 3) & 1) * 8 + (lane & 7);
    const int kA = (lane >> 4) * 8;
    // B x4: mats (n0k0),(n0k8),(n8k0),(n8k8)
    const int rB = (lane >> 4) * 8 + (lane & 7);
    const int kB = ((lane >> 3) & 1) * 8;

    const uint32_t aHiB = smem_u32(sAhi), aLoB = smem_u32(sAlo);
    const uint32_t bHiB = smem_u32(sBhi), bLoB = smem_u32(sBlo);

    for (int kc = 0; kc < 8; kc++) {
        const int k0 = kc * 32;
        __syncthreads();
        // ---- A fill: load fp32, split to hi/lo bf16 ----
#pragma unroll
        for (int i = 0; i < 4; i++) {
            int idx = tid + i * 256;          // 0..1023
            int row = idx >> 3, c = idx & 7;  // c-th float4 within 32-float row
            float4 v = make_float4(0.f, 0.f, 0.f, 0.f);
            if (bm + row < M)
                v = __ldg(reinterpret_cast<const float4*>(
                        X + (size_t)(bm + row) * IN_F + k0 + c * 4));
            __nv_bfloat16 h0 = __float2bfloat16_rn(v.x);
            __nv_bfloat16 h1 = __float2bfloat16_rn(v.y);
            __nv_bfloat16 h2 = __float2bfloat16_rn(v.z);
            __nv_bfloat16 h3 = __float2bfloat16_rn(v.w);
            uint2 ph = make_uint2(pack2(h0, h1), pack2(h2, h3));
            uint2 pl = make_uint2(
                pack2(__float2bfloat16_rn(v.x - __bfloat162float(h0)),
                      __float2bfloat16_rn(v.y - __bfloat162float(h1))),
                pack2(__float2bfloat16_rn(v.z - __bfloat162float(h2)),
                      __float2bfloat16_rn(v.w - __bfloat162float(h3))));
            *reinterpret_cast<uint2*>(&sAhi[row * SSTR + c * 4]) = ph;
            *reinterpret_cast<uint2*>(&sAlo[row * SSTR + c * 4]) = pl;
        }
        // ---- B fill: bf16 hi/lo straight copy ----
#pragma unroll
        for (int i = 0; i < 4; i++) {
            int idx = tid + i * 256;
            int row = idx >> 3, c = idx & 7;  // c-th 4-elem group in 32-k row
            *reinterpret_cast<uint2*>(&sBhi[row * SSTR + c * 4]) =
                __ldg(reinterpret_cast<const uint2*>(
                    g_Whi + (size_t)(bn + row) * IN_F + k0 + c * 4));
            *reinterpret_cast<uint2*>(&sBlo[row * SSTR + c * 4]) =
                __ldg(reinterpret_cast<const uint2*>(
                    g_Wlo + (size_t)(bn + row) * IN_F + k0 + c * 4));
        }
        __syncthreads();

#pragma unroll
        for (int ks = 0; ks < 2; ks++) {
            uint32_t a[2][4], b[4][4];
            const uint32_t kOffA = (uint32_t)((ks * 16 + kA) * 2);
            const uint32_t kOffB = (uint32_t)((ks * 16 + kB) * 2);
            // ---- P1: Ahi x Bhi ----
#pragma unroll
            for (int am = 0; am < 2; am++)
                ldsm4(a[am], aHiB + (wm + am * 16 + rA) * (SSTR * 2) + kOffA);
#pragma unroll
            for (int nb = 0; nb < 4; nb++)
                ldsm4(b[nb], bHiB + (wn + nb * 16 + rB) * (SSTR * 2) + kOffB);
#pragma unroll
            for (int am = 0; am < 2; am++)
#pragma unroll
                for (int j = 0; j < 8; j++)
                    mma16816(acc[am][j], a[am], &b[j >> 1][(j & 1) * 2]);
            // ---- P2: Ahi x Blo (A frags still live) ----
#pragma unroll
            for (int nb = 0; nb < 4; nb++)
                ldsm4(b[nb], bLoB + (wn + nb * 16 + rB) * (SSTR * 2) + kOffB);
#pragma unroll
            for (int am = 0; am < 2; am++)
#pragma unroll
                for (int j = 0; j < 8; j++)
                    mma16816(acc[am][j], a[am], &b[j >> 1][(j & 1) * 2]);
            // ---- P3: Alo x Bhi ----
#pragma unroll
            for (int am = 0; am < 2; am++)
                ldsm4(a[am], aLoB + (wm + am * 16 + rA) * (SSTR * 2) + kOffA);
#pragma unroll
            for (int nb = 0; nb < 4; nb++)
                ldsm4(b[nb], bHiB + (wn + nb * 16 + rB) * (SSTR * 2) + kOffB);
#pragma unroll
            for (int am = 0; am < 2; am++)
#pragma unroll
                for (int j = 0; j < 8; j++)
                    mma16816(acc[am][j], a[am], &b[j >> 1][(j & 1) * 2]);
        }
    }

    // ---- epilogue: c0,c1 -> row l/4; c2,c3 -> row l/4+8; col 2*(l%4) ----
    const int crow = lane >> 2, ccol = (lane & 3) * 2;
#pragma unroll
    for (int am = 0; am < 2; am++) {
#pragma unroll
        for (int j = 0; j < 8; j++) {
            int col = bn + wn + j * 8 + ccol;
            int r0  = bm + wm + am * 16 + crow;
            if (r0 < M)
                *reinterpret_cast<float2*>(out + (size_t)r0 * OUTSTRIDE + col) =
                    make_float2(acc[am][j][0], acc[am][j][1]);
            int r1 = r0 + 8;
            if (r1 < M)
                *reinterpret_cast<float2*>(out + (size_t)r1 * OUTSTRIDE + col) =
                    make_float2(acc[am][j][2], acc[am][j][3]);
        }
    }
}

// ---------------------------------------------------------------------------
// Edge scatter: 8 edges per warp-iteration for MLP.
// out[dst, 256+c] += val * out[src, c]; 128 features (one float4/lane)/pass.
// ---------------------------------------------------------------------------
__global__ __launch_bounds__(256)
void scatter_kernel(float* out, int E, int colOff) {
    const int lane   = threadIdx.x & 31;
    const int warpId = (blockIdx.x * blockDim.x + threadIdx.x) >> 5;
    const int nW     = (gridDim.x * blockDim.x) >> 5;

    for (int base = warpId * 8; base + 8 <= E; base += nW * 8) {
        int4 rec;
        if (lane < 8) rec = __ldg(&g_edges[base + lane]);
        int s[8], d[8];
        float v[8];
#pragma unroll
        for (int j = 0; j < 8; j++) {
            s[j] = __shfl_sync(0xffffffffu, rec.x, j);
            d[j] = __shfl_sync(0xffffffffu, rec.y, j);
            v[j] = __int_as_float(__shfl_sync(0xffffffffu, rec.z, j));
        }
        float4 g[8];
#pragma unroll
        for (int j = 0; j < 8; j++)
            g[j] = __ldg(reinterpret_cast<const float4*>(
                             out + (size_t)s[j] * OUTSTRIDE + colOff) + lane);
#pragma unroll
        for (int j = 0; j < 8; j++) {
            float* dp = out + (size_t)d[j] * OUTSTRIDE + OUT_F + colOff + lane * 4;
            asm volatile("red.global.add.v4.f32 [%0], {%1,%2,%3,%4};"
                         :: "l"(dp), "f"(g[j].x * v[j]), "f"(g[j].y * v[j]),
                            "f"(g[j].z * v[j]), "f"(g[j].w * v[j]) : "memory");
        }
    }
    // tail (only if E % 8 != 0)
    if (warpId == 0) {
        for (int e = E & ~7; e < E; e++) {
            int4 rec = __ldg(&g_edges[e]);
            float4 g = __ldg(reinterpret_cast<const float4*>(
                                 out + (size_t)rec.x * OUTSTRIDE + colOff) + lane);
            float v = __int_as_float(rec.z);
            float* dp = out + (size_t)rec.y * OUTSTRIDE + OUT_F + colOff + lane * 4;
            asm volatile("red.global.add.v4.f32 [%0], {%1,%2,%3,%4};"
                         :: "l"(dp), "f"(g.x * v), "f"(g.y * v),
                            "f"(g.z * v), "f"(g.w * v) : "memory");
        }
    }
}

// ---------------------------------------------------------------------------
extern "C" void kernel_launch(void* const* d_in, const int* in_sizes, int n_in,
                              void* d_out, int out_size) {
    const float* input  = (const float*)d_in[0];   // [N, 256]
    const void*  esrc   = d_in[1];
    const void*  edst   = d_in[2];
    const float* evals  = (const float*)d_in[3];
    const float* weight = (const float*)d_in[4];   // [256, 256]
    float* out = (float*)d_out;                    // [N, 512]

    const int M = in_sizes[0] / IN_F;              // 100000
    const int E = in_sizes[1];                     // 3200000

    detect_idx_kernel<<<1, 256>>>((const unsigned*)esrc);

    int zt = M * (OUT_F / 4);
    zero_neighbor_kernel<<<(zt + 255) / 256, 256>>>(out, M);
    conv_w_kernel<<<(IN_F * OUT_F) / 256, 256>>>(weight);
    pack_edges_kernel<<<(E + 255) / 256, 256>>>(esrc, edst, evals, E);

    dim3 gg((M + 127) / 128, OUT_F / 128);
    gemm_mma_kernel<<<gg, 256>>>(input, out, M);

    scatter_kernel<<<1184, 256>>>(out, E, 0);
    scatter_kernel<<<1184, 256>>>(out, E, 128);
}

// round 6
// speedup vs baseline: 1.4611x; 1.2488x over previous
#include <cuda_runtime.h>
#include <cuda_bf16.h>
#include <cstdint>

#define IN_F      256
#define OUT_F     256
#define OUTSTRIDE 512
#define MAXE      3200000
#define NB        100352          // 392 * 256 bins (>= N_NODES)

// ---------------- device scratch (allocation-free rule) ---------------------
__device__ __nv_bfloat16 g_Whi[OUT_F * IN_F];   // transposed: [n][k]
__device__ __nv_bfloat16 g_Wlo[OUT_F * IN_F];
__device__ int4          g_sorted[MAXE];        // {src, dst, val_bits, 0}, sorted by dst
__device__ int           g_hist[NB];
__device__ int           g_offs[NB];
__device__ int           g_bsum[512];
__device__ unsigned      g_idx_is64;

// ---------------- helpers ---------------------------------------------------
static __device__ __forceinline__ uint32_t smem_u32(const void* p) {
    uint32_t a;
    asm("{ .reg .u64 t; cvta.to.shared.u64 t, %1; cvt.u32.u64 %0, t; }"
        : "=r"(a) : "l"(p));
    return a;
}
static __device__ __forceinline__ void ldsm4(uint32_t* r, uint32_t addr) {
    asm volatile("ldmatrix.sync.aligned.m8n8.x4.shared.b16 {%0,%1,%2,%3}, [%4];"
                 : "=r"(r[0]), "=r"(r[1]), "=r"(r[2]), "=r"(r[3]) : "r"(addr));
}
static __device__ __forceinline__ void mma16816(float* c, const uint32_t* a,
                                                const uint32_t* b) {
    asm volatile(
        "mma.sync.aligned.m16n8k16.row.col.f32.bf16.bf16.f32 "
        "{%0,%1,%2,%3}, {%4,%5,%6,%7}, {%8,%9}, {%0,%1,%2,%3};"
        : "+f"(c[0]), "+f"(c[1]), "+f"(c[2]), "+f"(c[3])
        : "r"(a[0]), "r"(a[1]), "r"(a[2]), "r"(a[3]), "r"(b[0]), "r"(b[1]));
}
static __device__ __forceinline__ uint32_t pack2(__nv_bfloat16 a, __nv_bfloat16 b) {
    return ((uint32_t)__bfloat16_as_ushort(b) << 16) | __bfloat16_as_ushort(a);
}
// block-wide inclusive scan (blockDim multiple of 32, <= 1024)
static __device__ __forceinline__ int block_incl_scan(int v, int* shWarp) {
    const int lane = threadIdx.x & 31, w = threadIdx.x >> 5;
#pragma unroll
    for (int o = 1; o < 32; o <<= 1) {
        int t = __shfl_up_sync(0xffffffffu, v, o);
        if (lane >= o) v += t;
    }
    if (lane == 31) shWarp[w] = v;
    __syncthreads();
    if (w == 0) {
        const int nw = blockDim.x >> 5;
        int s = (lane < nw) ? shWarp[lane] : 0;
#pragma unroll
        for (int o = 1; o < 32; o <<= 1) {
            int t = __shfl_up_sync(0xffffffffu, s, o);
            if (lane >= o) s += t;
        }
        if (lane < nw) shWarp[lane] = s;
    }
    __syncthreads();
    if (w > 0) v += shWarp[w - 1];
    return v;
}

// ---------------------------------------------------------------------------
// Index-width detection (int64 vs int32 edge indices).
// ---------------------------------------------------------------------------
__global__ void detect_idx_kernel(const unsigned* __restrict__ p) {
    unsigned v = p[2 * threadIdx.x + 1];
    int any = __syncthreads_or(v != 0u);
    if (threadIdx.x == 0) g_idx_is64 = any ? 0u : 1u;
}

// ---------------------------------------------------------------------------
// Zero the ft_neighbor half of the output; also zero the histogram.
// ---------------------------------------------------------------------------
__global__ void zero_kernel(float* __restrict__ out, int M) {
    int idx = blockIdx.x * blockDim.x + threadIdx.x;
    if (idx < NB) g_hist[idx] = 0;
    int total = M * (OUT_F / 4);
    if (idx < total) {
        int row = idx >> 6;
        int c4  = idx & 63;
        reinterpret_cast<float4*>(out + (size_t)row * OUTSTRIDE + OUT_F)[c4] =
            make_float4(0.f, 0.f, 0.f, 0.f);
    }
}

// ---------------------------------------------------------------------------
// W[k][n] -> transposed bf16 hi/lo: g_W{hi,lo}[n][k].
// ---------------------------------------------------------------------------
__global__ void conv_w_kernel(const float* __restrict__ W) {
    int i = blockIdx.x * blockDim.x + threadIdx.x;   // 65536
    int k = i >> 8, n = i & 255;
    float x = W[i];
    __nv_bfloat16 h = __float2bfloat16_rn(x);
    g_Whi[n * IN_F + k] = h;
    g_Wlo[n * IN_F + k] = __float2bfloat16_rn(x - __bfloat162float(h));
}

// ---------------------------------------------------------------------------
// Counting sort by dst: histogram -> scan -> scatter.
// ---------------------------------------------------------------------------
__global__ void hist_kernel(const void* __restrict__ edst, int E) {
    int i = blockIdx.x * blockDim.x + threadIdx.x;
    if (i >= E) return;
    int d = g_idx_is64 ? (int)__ldg((const long long*)edst + i)
                       : __ldg((const int*)edst + i);
    atomicAdd(&g_hist[d], 1);
}
__global__ void scanA_kernel() {            // grid 392, block 256
    __shared__ int shW[8];
    int i = blockIdx.x * 256 + threadIdx.x;
    int v = g_hist[i];
    int inc = block_incl_scan(v, shW);
    g_offs[i] = inc - v;                     // block-local exclusive
    if (threadIdx.x == 255) g_bsum[blockIdx.x] = inc;
}
__global__ void scanB_kernel() {            // grid 1, block 512
    __shared__ int shW[16];
    int t = threadIdx.x;
    int v = (t < 392) ? g_bsum[t] : 0;
    int inc = block_incl_scan(v, shW);
    if (t < 392) g_bsum[t] = inc - v;        // exclusive block offsets
}
__global__ void scanC_kernel() {            // grid 392, block 256
    g_offs[blockIdx.x * 256 + threadIdx.x] += g_bsum[blockIdx.x];
}
__global__ void sort_scatter_kernel(const void* __restrict__ esrc,
                                    const void* __restrict__ edst,
                                    const float* __restrict__ ev, int E) {
    int i = blockIdx.x * blockDim.x + threadIdx.x;
    if (i >= E) return;
    int s, d;
    if (g_idx_is64) {
        s = (int)__ldg((const long long*)esrc + i);
        d = (int)__ldg((const long long*)edst + i);
    } else {
        s = __ldg((const int*)esrc + i);
        d = __ldg((const int*)edst + i);
    }
    int pos = atomicAdd(&g_offs[d], 1);
    g_sorted[pos] = make_int4(s, d, __float_as_int(__ldg(ev + i)), 0);
}

// ---------------------------------------------------------------------------
// GEMM via mma.sync (HMMA.16816 bf16), split-bf16 3-product.
// Block 128x128, 8 warps (warp tile 32x64), K-chunk 32, K=256.
// ---------------------------------------------------------------------------
#define SSTR 40

__global__ __launch_bounds__(256)
void gemm_mma_kernel(const float* __restrict__ X, float* __restrict__ out, int M) {
    __shared__ __align__(16) __nv_bfloat16 sAhi[128 * SSTR];
    __shared__ __align__(16) __nv_bfloat16 sAlo[128 * SSTR];
    __shared__ __align__(16) __nv_bfloat16 sBhi[128 * SSTR];
    __shared__ __align__(16) __nv_bfloat16 sBlo[128 * SSTR];

    const int tid  = threadIdx.x;
    const int lane = tid & 31, wid = tid >> 5;
    const int bm = blockIdx.x * 128;
    const int bn = blockIdx.y * 128;
    const int wm = (wid & 3) * 32;
    const int wn = (wid >> 2) * 64;

    float acc[2][8][4];
#pragma unroll
    for (int i = 0; i < 2; i++)
#pragma unroll
        for (int j = 0; j < 8; j++)
#pragma unroll
            for (int k = 0; k < 4; k++) acc[i][j][k] = 0.f;

    const int rA = ((lane >> 3) & 1) * 8 + (lane & 7);
    const int kA = (lane >> 4) * 8;
    const int rB = (lane >> 4) * 8 + (lane & 7);
    const int kB = ((lane >> 3) & 1) * 8;

    const uint32_t aHiB = smem_u32(sAhi), aLoB = smem_u32(sAlo);
    const uint32_t bHiB = smem_u32(sBhi), bLoB = smem_u32(sBlo);

    for (int kc = 0; kc < 8; kc++) {
        const int k0 = kc * 32;
        __syncthreads();
#pragma unroll
        for (int i = 0; i < 4; i++) {
            int idx = tid + i * 256;
            int row = idx >> 3, c = idx & 7;
            float4 v = make_float4(0.f, 0.f, 0.f, 0.f);
            if (bm + row < M)
                v = __ldg(reinterpret_cast<const float4*>(
                        X + (size_t)(bm + row) * IN_F + k0 + c * 4));
            __nv_bfloat16 h0 = __float2bfloat16_rn(v.x);
            __nv_bfloat16 h1 = __float2bfloat16_rn(v.y);
            __nv_bfloat16 h2 = __float2bfloat16_rn(v.z);
            __nv_bfloat16 h3 = __float2bfloat16_rn(v.w);
            uint2 ph = make_uint2(pack2(h0, h1), pack2(h2, h3));
            uint2 pl = make_uint2(
                pack2(__float2bfloat16_rn(v.x - __bfloat162float(h0)),
                      __float2bfloat16_rn(v.y - __bfloat162float(h1))),
                pack2(__float2bfloat16_rn(v.z - __bfloat162float(h2)),
                      __float2bfloat16_rn(v.w - __bfloat162float(h3))));
            *reinterpret_cast<uint2*>(&sAhi[row * SSTR + c * 4]) = ph;
            *reinterpret_cast<uint2*>(&sAlo[row * SSTR + c * 4]) = pl;
        }
#pragma unroll
        for (int i = 0; i < 4; i++) {
            int idx = tid + i * 256;
            int row = idx >> 3, c = idx & 7;
            *reinterpret_cast<uint2*>(&sBhi[row * SSTR + c * 4]) =
                __ldg(reinterpret_cast<const uint2*>(
                    g_Whi + (size_t)(bn + row) * IN_F + k0 + c * 4));
            *reinterpret_cast<uint2*>(&sBlo[row * SSTR + c * 4]) =
                __ldg(reinterpret_cast<const uint2*>(
                    g_Wlo + (size_t)(bn + row) * IN_F + k0 + c * 4));
        }
        __syncthreads();

#pragma unroll
        for (int ks = 0; ks < 2; ks++) {
            uint32_t a[2][4], b[4][4];
            const uint32_t kOffA = (uint32_t)((ks * 16 + kA) * 2);
            const uint32_t kOffB = (uint32_t)((ks * 16 + kB) * 2);
#pragma unroll
            for (int am = 0; am < 2; am++)
                ldsm4(a[am], aHiB + (wm + am * 16 + rA) * (SSTR * 2) + kOffA);
#pragma unroll
            for (int nb = 0; nb < 4; nb++)
                ldsm4(b[nb], bHiB + (wn + nb * 16 + rB) * (SSTR * 2) + kOffB);
#pragma unroll
            for (int am = 0; am < 2; am++)
#pragma unroll
                for (int j = 0; j < 8; j++)
                    mma16816(acc[am][j], a[am], &b[j >> 1][(j & 1) * 2]);
#pragma unroll
            for (int nb = 0; nb < 4; nb++)
                ldsm4(b[nb], bLoB + (wn + nb * 16 + rB) * (SSTR * 2) + kOffB);
#pragma unroll
            for (int am = 0; am < 2; am++)
#pragma unroll
                for (int j = 0; j < 8; j++)
                    mma16816(acc[am][j], a[am], &b[j >> 1][(j & 1) * 2]);
#pragma unroll
            for (int am = 0; am < 2; am++)
                ldsm4(a[am], aLoB + (wm + am * 16 + rA) * (SSTR * 2) + kOffA);
#pragma unroll
            for (int nb = 0; nb < 4; nb++)
                ldsm4(b[nb], bHiB + (wn + nb * 16 + rB) * (SSTR * 2) + kOffB);
#pragma unroll
            for (int am = 0; am < 2; am++)
#pragma unroll
                for (int j = 0; j < 8; j++)
                    mma16816(acc[am][j], a[am], &b[j >> 1][(j & 1) * 2]);
        }
    }

    const int crow = lane >> 2, ccol = (lane & 3) * 2;
#pragma unroll
    for (int am = 0; am < 2; am++) {
#pragma unroll
        for (int j = 0; j < 8; j++) {
            int col = bn + wn + j * 8 + ccol;
            int r0  = bm + wm + am * 16 + crow;
            if (r0 < M)
                *reinterpret_cast<float2*>(out + (size_t)r0 * OUTSTRIDE + col) =
                    make_float2(acc[am][j][0], acc[am][j][1]);
            int r1 = r0 + 8;
            if (r1 < M)
                *reinterpret_cast<float2*>(out + (size_t)r1 * OUTSTRIDE + col) =
                    make_float2(acc[am][j][2], acc[am][j][3]);
        }
    }
}

// ---------------------------------------------------------------------------
// Sorted scatter: edges sorted by dst -> register-accumulate runs, one
// red.global.add.v4 per dst-run. 8-edge batches keep gather MLP high.
// ---------------------------------------------------------------------------
static __device__ __forceinline__ void flush_run(float* out, int dstn, int colOff,
                                                 int lane, float4 a) {
    float* dp = out + (size_t)dstn * OUTSTRIDE + OUT_F + colOff + lane * 4;
    asm volatile("red.global.add.v4.f32 [%0], {%1,%2,%3,%4};"
                 :: "l"(dp), "f"(a.x), "f"(a.y), "f"(a.z), "f"(a.w) : "memory");
}

__global__ __launch_bounds__(256)
void scatter_sorted_kernel(float* out, int E, int colOff) {
    const int lane   = threadIdx.x & 31;
    const int warpId = (blockIdx.x * blockDim.x + threadIdx.x) >> 5;
    const int nW     = (gridDim.x * blockDim.x) >> 5;

    const int per = (E + nW - 1) / nW;
    const int e0 = warpId * per;
    const int e1 = min(E, e0 + per);
    if (e0 >= e1) return;

    float4 acc = make_float4(0.f, 0.f, 0.f, 0.f);
    int cur = -1;

    for (int base = e0; base < e1; base += 8) {
        const int cnt = min(8, e1 - base);
        int4 rec;
        if (lane < cnt) rec = __ldg(&g_sorted[base + lane]);
        int d[8]; float v[8]; float4 g[8];
#pragma unroll
        for (int j = 0; j < 8; j++) {
            int sj = __shfl_sync(0xffffffffu, rec.x, j);
            d[j]   = __shfl_sync(0xffffffffu, rec.y, j);
            v[j]   = __int_as_float(__shfl_sync(0xffffffffu, rec.z, j));
            if (j < cnt)
                g[j] = __ldg(reinterpret_cast<const float4*>(
                                 out + (size_t)sj * OUTSTRIDE + colOff) + lane);
        }
#pragma unroll
        for (int j = 0; j < 8; j++) {
            if (j < cnt) {
                if (d[j] != cur) {
                    if (cur >= 0) flush_run(out, cur, colOff, lane, acc);
                    cur = d[j];
                    acc = make_float4(0.f, 0.f, 0.f, 0.f);
                }
                acc.x += v[j] * g[j].x;
                acc.y += v[j] * g[j].y;
                acc.z += v[j] * g[j].z;
                acc.w += v[j] * g[j].w;
            }
        }
    }
    if (cur >= 0) flush_run(out, cur, colOff, lane, acc);
}

// ---------------------------------------------------------------------------
extern "C" void kernel_launch(void* const* d_in, const int* in_sizes, int n_in,
                              void* d_out, int out_size) {
    const float* input  = (const float*)d_in[0];   // [N, 256]
    const void*  esrc   = d_in[1];
    const void*  edst   = d_in[2];
    const float* evals  = (const float*)d_in[3];
    const float* weight = (const float*)d_in[4];   // [256, 256]
    float* out = (float*)d_out;                    // [N, 512]

    const int M = in_sizes[0] / IN_F;              // 100000
    const int E = in_sizes[1];                     // 3200000

    detect_idx_kernel<<<1, 256>>>((const unsigned*)esrc);

    int zt = M * (OUT_F / 4);
    zero_kernel<<<(zt + 255) / 256, 256>>>(out, M);
    conv_w_kernel<<<(IN_F * OUT_F) / 256, 256>>>(weight);

    // counting sort by dst
    hist_kernel<<<(E + 255) / 256, 256>>>(edst, E);
    scanA_kernel<<<NB / 256, 256>>>();
    scanB_kernel<<<1, 512>>>();
    scanC_kernel<<<NB / 256, 256>>>();
    sort_scatter_kernel<<<(E + 255) / 256, 256>>>(esrc, edst, evals, E);

    dim3 gg((M + 127) / 128, OUT_F / 128);
    gemm_mma_kernel<<<gg, 256>>>(input, out, M);

    scatter_sorted_kernel<<<1184, 256>>>(out, E, 0);
    scatter_sorted_kernel<<<1184, 256>>>(out, E, 128);
}

// round 7
// speedup vs baseline: 2.1212x; 1.4518x over previous
#include <cuda_runtime.h>
#include <cuda_bf16.h>
#include <cstdint>

#define IN_F      256
#define OUT_F     256
#define OUTSTRIDE 512
#define MAXE      3200000
#define NB        100352          // 392 * 256 bins (>= N_NODES)

// ---------------- device scratch (allocation-free rule) ---------------------
__device__ __nv_bfloat16 g_Whi[OUT_F * IN_F];   // transposed: [n][k]
__device__ __nv_bfloat16 g_Wlo[OUT_F * IN_F];
__device__ int2          g_pack[MAXE];          // {src, val_bits}, sorted by dst
__device__ int           g_hist[NB];
__device__ int           g_offs[NB];
__device__ int           g_bsum[512];
__device__ unsigned      g_idx_is64;

// ---------------- helpers ---------------------------------------------------
static __device__ __forceinline__ uint32_t smem_u32(const void* p) {
    uint32_t a;
    asm("{ .reg .u64 t; cvta.to.shared.u64 t, %1; cvt.u32.u64 %0, t; }"
        : "=r"(a) : "l"(p));
    return a;
}
static __device__ __forceinline__ void ldsm4(uint32_t* r, uint32_t addr) {
    asm volatile("ldmatrix.sync.aligned.m8n8.x4.shared.b16 {%0,%1,%2,%3}, [%4];"
                 : "=r"(r[0]), "=r"(r[1]), "=r"(r[2]), "=r"(r[3]) : "r"(addr));
}
static __device__ __forceinline__ void mma16816(float* c, const uint32_t* a,
                                                const uint32_t* b) {
    asm volatile(
        "mma.sync.aligned.m16n8k16.row.col.f32.bf16.bf16.f32 "
        "{%0,%1,%2,%3}, {%4,%5,%6,%7}, {%8,%9}, {%0,%1,%2,%3};"
        : "+f"(c[0]), "+f"(c[1]), "+f"(c[2]), "+f"(c[3])
        : "r"(a[0]), "r"(a[1]), "r"(a[2]), "r"(a[3]), "r"(b[0]), "r"(b[1]));
}
static __device__ __forceinline__ uint32_t pack2(__nv_bfloat16 a, __nv_bfloat16 b) {
    return ((uint32_t)__bfloat16_as_ushort(b) << 16) | __bfloat16_as_ushort(a);
}
// block-wide inclusive scan (blockDim multiple of 32, <= 1024)
static __device__ __forceinline__ int block_incl_scan(int v, int* shWarp) {
    const int lane = threadIdx.x & 31, w = threadIdx.x >> 5;
#pragma unroll
    for (int o = 1; o < 32; o <<= 1) {
        int t = __shfl_up_sync(0xffffffffu, v, o);
        if (lane >= o) v += t;
    }
    if (lane == 31) shWarp[w] = v;
    __syncthreads();
    if (w == 0) {
        const int nw = blockDim.x >> 5;
        int s = (lane < nw) ? shWarp[lane] : 0;
#pragma unroll
        for (int o = 1; o < 32; o <<= 1) {
            int t = __shfl_up_sync(0xffffffffu, s, o);
            if (lane >= o) s += t;
        }
        if (lane < nw) shWarp[lane] = s;
    }
    __syncthreads();
    if (w > 0) v += shWarp[w - 1];
    return v;
}

// ---------------------------------------------------------------------------
__global__ void detect_idx_kernel(const unsigned* __restrict__ p) {
    unsigned v = p[2 * threadIdx.x + 1];
    int any = __syncthreads_or(v != 0u);
    if (threadIdx.x == 0) g_idx_is64 = any ? 0u : 1u;
}

__global__ void zero_hist_kernel() {
    g_hist[blockIdx.x * 256 + threadIdx.x] = 0;
}

// Zero the ft_neighbor half of the output (covers empty dst nodes).
__global__ void zero_out_kernel(float* __restrict__ out, int M) {
    int idx = blockIdx.x * blockDim.x + threadIdx.x;
    int total = M * (OUT_F / 4);
    if (idx < total) {
        int row = idx >> 6;
        int c4  = idx & 63;
        reinterpret_cast<float4*>(out + (size_t)row * OUTSTRIDE + OUT_F)[c4] =
            make_float4(0.f, 0.f, 0.f, 0.f);
    }
}

// W[k][n] -> transposed bf16 hi/lo: g_W{hi,lo}[n][k].
__global__ void conv_w_kernel(const float* __restrict__ W) {
    int i = blockIdx.x * blockDim.x + threadIdx.x;   // 65536
    int k = i >> 8, n = i & 255;
    float x = W[i];
    __nv_bfloat16 h = __float2bfloat16_rn(x);
    g_Whi[n * IN_F + k] = h;
    g_Wlo[n * IN_F + k] = __float2bfloat16_rn(x - __bfloat162float(h));
}

// ---------------------------------------------------------------------------
// Counting sort by dst: histogram -> scan -> scatter into 8B records.
// After sort_pack_kernel, g_offs[d] = END offset of d's run; start = end-hist.
// ---------------------------------------------------------------------------
__global__ void hist_kernel(const void* __restrict__ edst, int E) {
    int i = blockIdx.x * blockDim.x + threadIdx.x;
    if (i >= E) return;
    int d = g_idx_is64 ? (int)__ldg((const long long*)edst + i)
                       : __ldg((const int*)edst + i);
    atomicAdd(&g_hist[d], 1);
}
__global__ void scanA_kernel() {            // grid 392, block 256
    __shared__ int shW[8];
    int i = blockIdx.x * 256 + threadIdx.x;
    int v = g_hist[i];
    int inc = block_incl_scan(v, shW);
    g_offs[i] = inc - v;
    if (threadIdx.x == 255) g_bsum[blockIdx.x] = inc;
}
__global__ void scanB_kernel() {            // grid 1, block 512
    __shared__ int shW[16];
    int t = threadIdx.x;
    int v = (t < 392) ? g_bsum[t] : 0;
    int inc = block_incl_scan(v, shW);
    if (t < 392) g_bsum[t] = inc - v;
}
__global__ void scanC_kernel() {            // grid 392, block 256
    g_offs[blockIdx.x * 256 + threadIdx.x] += g_bsum[blockIdx.x];
}
__global__ void sort_pack_kernel(const void* __restrict__ esrc,
                                 const void* __restrict__ edst,
                                 const float* __restrict__ ev, int E) {
    int i = blockIdx.x * blockDim.x + threadIdx.x;
    if (i >= E) return;
    int s, d;
    if (g_idx_is64) {
        s = (int)__ldg((const long long*)esrc + i);
        d = (int)__ldg((const long long*)edst + i);
    } else {
        s = __ldg((const int*)esrc + i);
        d = __ldg((const int*)edst + i);
    }
    int pos = atomicAdd(&g_offs[d], 1);
    g_pack[pos] = make_int2(s, __float_as_int(__ldg(ev + i)));
}

// ---------------------------------------------------------------------------
// GEMM via mma.sync (HMMA.16816 bf16), split-bf16 3-product.
// Block 128x128, 8 warps (warp tile 32x64), K-chunk 32, K=256.
// bnBase selects the N-half (0 or 128) so halves can run on separate streams.
// ---------------------------------------------------------------------------
#define SSTR 40

__global__ __launch_bounds__(256)
void gemm_mma_kernel(const float* __restrict__ X, float* __restrict__ out,
                     int M, int bnBase) {
    __shared__ __align__(16) __nv_bfloat16 sAhi[128 * SSTR];
    __shared__ __align__(16) __nv_bfloat16 sAlo[128 * SSTR];
    __shared__ __align__(16) __nv_bfloat16 sBhi[128 * SSTR];
    __shared__ __align__(16) __nv_bfloat16 sBlo[128 * SSTR];

    const int tid  = threadIdx.x;
    const int lane = tid & 31, wid = tid >> 5;
    const int bm = blockIdx.x * 128;
    const int bn = bnBase;
    const int wm = (wid & 3) * 32;
    const int wn = (wid >> 2) * 64;

    float acc[2][8][4];
#pragma unroll
    for (int i = 0; i < 2; i++)
#pragma unroll
        for (int j = 0; j < 8; j++)
#pragma unroll
            for (int k = 0; k < 4; k++) acc[i][j][k] = 0.f;

    const int rA = ((lane >> 3) & 1) * 8 + (lane & 7);
    const int kA = (lane >> 4) * 8;
    const int rB = (lane >> 4) * 8 + (lane & 7);
    const int kB = ((lane >> 3) & 1) * 8;

    const uint32_t aHiB = smem_u32(sAhi), aLoB = smem_u32(sAlo);
    const uint32_t bHiB = smem_u32(sBhi), bLoB = smem_u32(sBlo);

    for (int kc = 0; kc < 8; kc++) {
        const int k0 = kc * 32;
        __syncthreads();
#pragma unroll
        for (int i = 0; i < 4; i++) {
            int idx = tid + i * 256;
            int row = idx >> 3, c = idx & 7;
            float4 v = make_float4(0.f, 0.f, 0.f, 0.f);
            if (bm + row < M)
                v = __ldg(reinterpret_cast<const float4*>(
                        X + (size_t)(bm + row) * IN_F + k0 + c * 4));
            __nv_bfloat16 h0 = __float2bfloat16_rn(v.x);
            __nv_bfloat16 h1 = __float2bfloat16_rn(v.y);
            __nv_bfloat16 h2 = __float2bfloat16_rn(v.z);
            __nv_bfloat16 h3 = __float2bfloat16_rn(v.w);
            uint2 ph = make_uint2(pack2(h0, h1), pack2(h2, h3));
            uint2 pl = make_uint2(
                pack2(__float2bfloat16_rn(v.x - __bfloat162float(h0)),
                      __float2bfloat16_rn(v.y - __bfloat162float(h1))),
                pack2(__float2bfloat16_rn(v.z - __bfloat162float(h2)),
                      __float2bfloat16_rn(v.w - __bfloat162float(h3))));
            *reinterpret_cast<uint2*>(&sAhi[row * SSTR + c * 4]) = ph;
            *reinterpret_cast<uint2*>(&sAlo[row * SSTR + c * 4]) = pl;
        }
#pragma unroll
        for (int i = 0; i < 4; i++) {
            int idx = tid + i * 256;
            int row = idx >> 3, c = idx & 7;
            *reinterpret_cast<uint2*>(&sBhi[row * SSTR + c * 4]) =
                __ldg(reinterpret_cast<const uint2*>(
                    g_Whi + (size_t)(bn + row) * IN_F + k0 + c * 4));
            *reinterpret_cast<uint2*>(&sBlo[row * SSTR + c * 4]) =
                __ldg(reinterpret_cast<const uint2*>(
                    g_Wlo + (size_t)(bn + row) * IN_F + k0 + c * 4));
        }
        __syncthreads();

#pragma unroll
        for (int ks = 0; ks < 2; ks++) {
            uint32_t a[2][4], b[4][4];
            const uint32_t kOffA = (uint32_t)((ks * 16 + kA) * 2);
            const uint32_t kOffB = (uint32_t)((ks * 16 + kB) * 2);
#pragma unroll
            for (int am = 0; am < 2; am++)
                ldsm4(a[am], aHiB + (wm + am * 16 + rA) * (SSTR * 2) + kOffA);
#pragma unroll
            for (int nb = 0; nb < 4; nb++)
                ldsm4(b[nb], bHiB + (wn + nb * 16 + rB) * (SSTR * 2) + kOffB);
#pragma unroll
            for (int am = 0; am < 2; am++)
#pragma unroll
                for (int j = 0; j < 8; j++)
                    mma16816(acc[am][j], a[am], &b[j >> 1][(j & 1) * 2]);
#pragma unroll
            for (int nb = 0; nb < 4; nb++)
                ldsm4(b[nb], bLoB + (wn + nb * 16 + rB) * (SSTR * 2) + kOffB);
#pragma unroll
            for (int am = 0; am < 2; am++)
#pragma unroll
                for (int j = 0; j < 8; j++)
                    mma16816(acc[am][j], a[am], &b[j >> 1][(j & 1) * 2]);
#pragma unroll
            for (int am = 0; am < 2; am++)
                ldsm4(a[am], aLoB + (wm + am * 16 + rA) * (SSTR * 2) + kOffA);
#pragma unroll
            for (int nb = 0; nb < 4; nb++)
                ldsm4(b[nb], bHiB + (wn + nb * 16 + rB) * (SSTR * 2) + kOffB);
#pragma unroll
            for (int am = 0; am < 2; am++)
#pragma unroll
                for (int j = 0; j < 8; j++)
                    mma16816(acc[am][j], a[am], &b[j >> 1][(j & 1) * 2]);
        }
    }

    const int crow = lane >> 2, ccol = (lane & 3) * 2;
#pragma unroll
    for (int am = 0; am < 2; am++) {
#pragma unroll
        for (int j = 0; j < 8; j++) {
            int col = bn + wn + j * 8 + ccol;
            int r0  = bm + wm + am * 16 + crow;
            if (r0 < M)
                *reinterpret_cast<float2*>(out + (size_t)r0 * OUTSTRIDE + col) =
                    make_float2(acc[am][j][0], acc[am][j][1]);
            int r1 = r0 + 8;
            if (r1 < M)
                *reinterpret_cast<float2*>(out + (size_t)r1 * OUTSTRIDE + col) =
                    make_float2(acc[am][j][2], acc[am][j][3]);
        }
    }
}

// ---------------------------------------------------------------------------
// CSR scatter: one warp per dst node; register accumulation; ONE plain
// STG.128 per node (no atomics). 128 features (one float4/lane) per pass.
// ---------------------------------------------------------------------------
__global__ __launch_bounds__(256)
void scatter_csr_kernel(float* out, int M, int colOff) {
    const int d    = (blockIdx.x * blockDim.x + threadIdx.x) >> 5;  // dst node
    const int lane = threadIdx.x & 31;
    if (d >= M) return;

    const int end   = g_offs[d];
    const int start = end - g_hist[d];
    if (start >= end) return;

    float4 acc = make_float4(0.f, 0.f, 0.f, 0.f);
    for (int base = start; base < end; base += 32) {
        const int n = min(32, end - base);
        int2 rec;
        if (lane < n) rec = __ldg(&g_pack[base + lane]);
        for (int j = 0; j < n; j++) {
            int   s = __shfl_sync(0xffffffffu, rec.x, j);
            float v = __int_as_float(__shfl_sync(0xffffffffu, rec.y, j));
            float4 g = __ldg(reinterpret_cast<const float4*>(
                                 out + (size_t)s * OUTSTRIDE + colOff) + lane);
            acc.x += v * g.x;
            acc.y += v * g.y;
            acc.z += v * g.z;
            acc.w += v * g.w;
        }
    }
    *reinterpret_cast<float4*>(out + (size_t)d * OUTSTRIDE + OUT_F + colOff +
                               lane * 4) = acc;
}

// ---------------------------------------------------------------------------
extern "C" void kernel_launch(void* const* d_in, const int* in_sizes, int n_in,
                              void* d_out, int out_size) {
    const float* input  = (const float*)d_in[0];   // [N, 256]
    const void*  esrc   = d_in[1];
    const void*  edst   = d_in[2];
    const float* evals  = (const float*)d_in[3];
    const float* weight = (const float*)d_in[4];   // [256, 256]
    float* out = (float*)d_out;                    // [N, 512]

    const int M = in_sizes[0] / IN_F;              // 100000
    const int E = in_sizes[1];                     // 3200000

    static cudaStream_t s1 = nullptr, s2 = nullptr;
    static cudaEvent_t evRoot, ev1, evG0, ev2;
    if (!s1) {   // one-time resource creation (not memory allocation)
        cudaStreamCreateWithFlags(&s1, cudaStreamNonBlocking);
        cudaStreamCreateWithFlags(&s2, cudaStreamNonBlocking);
        cudaEventCreateWithFlags(&evRoot, cudaEventDisableTiming);
        cudaEventCreateWithFlags(&ev1,    cudaEventDisableTiming);
        cudaEventCreateWithFlags(&evG0,   cudaEventDisableTiming);
        cudaEventCreateWithFlags(&ev2,    cudaEventDisableTiming);
    }

    // ---- fork side stream s1 for the sort chain ----
    cudaEventRecord(evRoot, 0);
    cudaStreamWaitEvent(s1, evRoot, 0);

    // s1: counting sort (independent of GEMM)
    zero_hist_kernel<<<NB / 256, 256, 0, s1>>>();
    detect_idx_kernel<<<1, 256, 0, s1>>>((const unsigned*)esrc);
    hist_kernel<<<(E + 255) / 256, 256, 0, s1>>>(edst, E);
    scanA_kernel<<<NB / 256, 256, 0, s1>>>();
    scanB_kernel<<<1, 512, 0, s1>>>();
    scanC_kernel<<<NB / 256, 256, 0, s1>>>();
    sort_pack_kernel<<<(E + 255) / 256, 256, 0, s1>>>(esrc, edst, evals, E);
    cudaEventRecord(ev1, s1);

    // s0 (capture stream): zero output, convert W, GEMM half 0 (cols 0-127)
    int zt = M * (OUT_F / 4);
    zero_out_kernel<<<(zt + 255) / 256, 256>>>(out, M);
    conv_w_kernel<<<(IN_F * OUT_F) / 256, 256>>>(weight);
    dim3 gg((M + 127) / 128, 1);
    gemm_mma_kernel<<<gg, 256>>>(input, out, M, 0);
    cudaEventRecord(evG0, 0);

    // s2: GEMM half 1 (cols 128-255), overlaps scatter pass 0
    cudaStreamWaitEvent(s2, evG0, 0);
    gemm_mma_kernel<<<gg, 256, 0, s2>>>(input, out, M, 128);
    cudaEventRecord(ev2, s2);

    // s0: scatter pass 0 (needs sort chain + gemm half 0)
    cudaStreamWaitEvent(0, ev1, 0);
    scatter_csr_kernel<<<(M + 7) / 8, 256>>>(out, M, 0);

    // s0: scatter pass 1 (needs gemm half 1)
    cudaStreamWaitEvent(0, ev2, 0);
    scatter_csr_kernel<<<(M + 7) / 8, 256>>>(out, M, 128);
}

// round 8
// speedup vs baseline: 2.3572x; 1.1112x over previous
#include <cuda_runtime.h>
#include <cuda_bf16.h>
#include <cuda_fp16.h>
#include <cstdint>

#define IN_F      256
#define OUT_F     256
#define OUTSTRIDE 512
#define MAXE      3200000
#define MAXM      100000
#define NB        100352          // 392 * 256 bins (>= N_NODES)

// ---------------- device scratch (allocation-free rule) ---------------------
__device__ __nv_bfloat16 g_Whi[OUT_F * IN_F];   // transposed: [n][k]
__device__ __nv_bfloat16 g_Wlo[OUT_F * IN_F];
__device__ __half        g_ftH[(size_t)MAXM * OUT_F];  // fp16 mirror of ft_input
__device__ int2          g_pack[MAXE];          // {src, val_bits}, sorted by dst
__device__ int           g_hist[NB];
__device__ int           g_offs[NB];
__device__ int           g_bsum[512];
__device__ unsigned      g_idx_is64;

// ---------------- helpers ---------------------------------------------------
static __device__ __forceinline__ uint32_t smem_u32(const void* p) {
    uint32_t a;
    asm("{ .reg .u64 t; cvta.to.shared.u64 t, %1; cvt.u32.u64 %0, t; }"
        : "=r"(a) : "l"(p));
    return a;
}
static __device__ __forceinline__ void ldsm4(uint32_t* r, uint32_t addr) {
    asm volatile("ldmatrix.sync.aligned.m8n8.x4.shared.b16 {%0,%1,%2,%3}, [%4];"
                 : "=r"(r[0]), "=r"(r[1]), "=r"(r[2]), "=r"(r[3]) : "r"(addr));
}
static __device__ __forceinline__ void mma16816(float* c, const uint32_t* a,
                                                const uint32_t* b) {
    asm volatile(
        "mma.sync.aligned.m16n8k16.row.col.f32.bf16.bf16.f32 "
        "{%0,%1,%2,%3}, {%4,%5,%6,%7}, {%8,%9}, {%0,%1,%2,%3};"
        : "+f"(c[0]), "+f"(c[1]), "+f"(c[2]), "+f"(c[3])
        : "r"(a[0]), "r"(a[1]), "r"(a[2]), "r"(a[3]), "r"(b[0]), "r"(b[1]));
}
static __device__ __forceinline__ uint32_t pack2(__nv_bfloat16 a, __nv_bfloat16 b) {
    return ((uint32_t)__bfloat16_as_ushort(b) << 16) | __bfloat16_as_ushort(a);
}
// block-wide inclusive scan (blockDim multiple of 32, <= 1024)
static __device__ __forceinline__ int block_incl_scan(int v, int* shWarp) {
    const int lane = threadIdx.x & 31, w = threadIdx.x >> 5;
#pragma unroll
    for (int o = 1; o < 32; o <<= 1) {
        int t = __shfl_up_sync(0xffffffffu, v, o);
        if (lane >= o) v += t;
    }
    if (lane == 31) shWarp[w] = v;
    __syncthreads();
    if (w == 0) {
        const int nw = blockDim.x >> 5;
        int s = (lane < nw) ? shWarp[lane] : 0;
#pragma unroll
        for (int o = 1; o < 32; o <<= 1) {
            int t = __shfl_up_sync(0xffffffffu, s, o);
            if (lane >= o) s += t;
        }
        if (lane < nw) shWarp[lane] = s;
    }
    __syncthreads();
    if (w > 0) v += shWarp[w - 1];
    return v;
}

// ---------------------------------------------------------------------------
__global__ void detect_idx_kernel(const unsigned* __restrict__ p) {
    unsigned v = p[2 * threadIdx.x + 1];
    int any = __syncthreads_or(v != 0u);
    if (threadIdx.x == 0) g_idx_is64 = any ? 0u : 1u;
}

__global__ void zero_hist_kernel() {
    g_hist[blockIdx.x * 256 + threadIdx.x] = 0;
}

// W[k][n] -> transposed bf16 hi/lo: g_W{hi,lo}[n][k].
__global__ void conv_w_kernel(const float* __restrict__ W) {
    int i = blockIdx.x * blockDim.x + threadIdx.x;   // 65536
    int k = i >> 8, n = i & 255;
    float x = W[i];
    __nv_bfloat16 h = __float2bfloat16_rn(x);
    g_Whi[n * IN_F + k] = h;
    g_Wlo[n * IN_F + k] = __float2bfloat16_rn(x - __bfloat162float(h));
}

// ---------------------------------------------------------------------------
// Counting sort by dst: histogram -> scan -> scatter into 8B records.
// After sort_pack_kernel, g_offs[d] = END offset of d's run; start = end-hist.
// ---------------------------------------------------------------------------
__global__ void hist_kernel(const void* __restrict__ edst, int E) {
    int i = blockIdx.x * blockDim.x + threadIdx.x;
    if (i >= E) return;
    int d = g_idx_is64 ? (int)__ldg((const long long*)edst + i)
                       : __ldg((const int*)edst + i);
    atomicAdd(&g_hist[d], 1);
}
__global__ void scanA_kernel() {            // grid 392, block 256
    __shared__ int shW[8];
    int i = blockIdx.x * 256 + threadIdx.x;
    int v = g_hist[i];
    int inc = block_incl_scan(v, shW);
    g_offs[i] = inc - v;
    if (threadIdx.x == 255) g_bsum[blockIdx.x] = inc;
}
__global__ void scanB_kernel() {            // grid 1, block 512
    __shared__ int shW[16];
    int t = threadIdx.x;
    int v = (t < 392) ? g_bsum[t] : 0;
    int inc = block_incl_scan(v, shW);
    if (t < 392) g_bsum[t] = inc - v;
}
__global__ void scanC_kernel() {            // grid 392, block 256
    g_offs[blockIdx.x * 256 + threadIdx.x] += g_bsum[blockIdx.x];
}
__global__ void sort_pack_kernel(const void* __restrict__ esrc,
                                 const void* __restrict__ edst,
                                 const float* __restrict__ ev, int E) {
    int i = blockIdx.x * blockDim.x + threadIdx.x;
    if (i >= E) return;
    int s, d;
    if (g_idx_is64) {
        s = (int)__ldg((const long long*)esrc + i);
        d = (int)__ldg((const long long*)edst + i);
    } else {
        s = __ldg((const int*)esrc + i);
        d = __ldg((const int*)edst + i);
    }
    int pos = atomicAdd(&g_offs[d], 1);
    g_pack[pos] = make_int2(s, __float_as_int(__ldg(ev + i)));
}

// ---------------------------------------------------------------------------
// GEMM via mma.sync (HMMA.16816 bf16), split-bf16 3-product.
// Block 128x128, 8 warps (warp tile 32x64), K-chunk 32, K=256.
// bnBase selects the N-half. Epilogue writes fp32 out AND fp16 mirror g_ftH.
// ---------------------------------------------------------------------------
#define SSTR 40

__global__ __launch_bounds__(256)
void gemm_mma_kernel(const float* __restrict__ X, float* __restrict__ out,
                     int M, int bnBase) {
    __shared__ __align__(16) __nv_bfloat16 sAhi[128 * SSTR];
    __shared__ __align__(16) __nv_bfloat16 sAlo[128 * SSTR];
    __shared__ __align__(16) __nv_bfloat16 sBhi[128 * SSTR];
    __shared__ __align__(16) __nv_bfloat16 sBlo[128 * SSTR];

    const int tid  = threadIdx.x;
    const int lane = tid & 31, wid = tid >> 5;
    const int bm = blockIdx.x * 128;
    const int bn = bnBase;
    const int wm = (wid & 3) * 32;
    const int wn = (wid >> 2) * 64;

    float acc[2][8][4];
#pragma unroll
    for (int i = 0; i < 2; i++)
#pragma unroll
        for (int j = 0; j < 8; j++)
#pragma unroll
            for (int k = 0; k < 4; k++) acc[i][j][k] = 0.f;

    const int rA = ((lane >> 3) & 1) * 8 + (lane & 7);
    const int kA = (lane >> 4) * 8;
    const int rB = (lane >> 4) * 8 + (lane & 7);
    const int kB = ((lane >> 3) & 1) * 8;

    const uint32_t aHiB = smem_u32(sAhi), aLoB = smem_u32(sAlo);
    const uint32_t bHiB = smem_u32(sBhi), bLoB = smem_u32(sBlo);

    for (int kc = 0; kc < 8; kc++) {
        const int k0 = kc * 32;
        __syncthreads();
#pragma unroll
        for (int i = 0; i < 4; i++) {
            int idx = tid + i * 256;
            int row = idx >> 3, c = idx & 7;
            float4 v = make_float4(0.f, 0.f, 0.f, 0.f);
            if (bm + row < M)
                v = __ldg(reinterpret_cast<const float4*>(
                        X + (size_t)(bm + row) * IN_F + k0 + c * 4));
            __nv_bfloat16 h0 = __float2bfloat16_rn(v.x);
            __nv_bfloat16 h1 = __float2bfloat16_rn(v.y);
            __nv_bfloat16 h2 = __float2bfloat16_rn(v.z);
            __nv_bfloat16 h3 = __float2bfloat16_rn(v.w);
            uint2 ph = make_uint2(pack2(h0, h1), pack2(h2, h3));
            uint2 pl = make_uint2(
                pack2(__float2bfloat16_rn(v.x - __bfloat162float(h0)),
                      __float2bfloat16_rn(v.y - __bfloat162float(h1))),
                pack2(__float2bfloat16_rn(v.z - __bfloat162float(h2)),
                      __float2bfloat16_rn(v.w - __bfloat162float(h3))));
            *reinterpret_cast<uint2*>(&sAhi[row * SSTR + c * 4]) = ph;
            *reinterpret_cast<uint2*>(&sAlo[row * SSTR + c * 4]) = pl;
        }
#pragma unroll
        for (int i = 0; i < 4; i++) {
            int idx = tid + i * 256;
            int row = idx >> 3, c = idx & 7;
            *reinterpret_cast<uint2*>(&sBhi[row * SSTR + c * 4]) =
                __ldg(reinterpret_cast<const uint2*>(
                    g_Whi + (size_t)(bn + row) * IN_F + k0 + c * 4));
            *reinterpret_cast<uint2*>(&sBlo[row * SSTR + c * 4]) =
                __ldg(reinterpret_cast<const uint2*>(
                    g_Wlo + (size_t)(bn + row) * IN_F + k0 + c * 4));
        }
        __syncthreads();

#pragma unroll
        for (int ks = 0; ks < 2; ks++) {
            uint32_t a[2][4], b[4][4];
            const uint32_t kOffA = (uint32_t)((ks * 16 + kA) * 2);
            const uint32_t kOffB = (uint32_t)((ks * 16 + kB) * 2);
#pragma unroll
            for (int am = 0; am < 2; am++)
                ldsm4(a[am], aHiB + (wm + am * 16 + rA) * (SSTR * 2) + kOffA);
#pragma unroll
            for (int nb = 0; nb < 4; nb++)
                ldsm4(b[nb], bHiB + (wn + nb * 16 + rB) * (SSTR * 2) + kOffB);
#pragma unroll
            for (int am = 0; am < 2; am++)
#pragma unroll
                for (int j = 0; j < 8; j++)
                    mma16816(acc[am][j], a[am], &b[j >> 1][(j & 1) * 2]);
#pragma unroll
            for (int nb = 0; nb < 4; nb++)
                ldsm4(b[nb], bLoB + (wn + nb * 16 + rB) * (SSTR * 2) + kOffB);
#pragma unroll
            for (int am = 0; am < 2; am++)
#pragma unroll
                for (int j = 0; j < 8; j++)
                    mma16816(acc[am][j], a[am], &b[j >> 1][(j & 1) * 2]);
#pragma unroll
            for (int am = 0; am < 2; am++)
                ldsm4(a[am], aLoB + (wm + am * 16 + rA) * (SSTR * 2) + kOffA);
#pragma unroll
            for (int nb = 0; nb < 4; nb++)
                ldsm4(b[nb], bHiB + (wn + nb * 16 + rB) * (SSTR * 2) + kOffB);
#pragma unroll
            for (int am = 0; am < 2; am++)
#pragma unroll
                for (int j = 0; j < 8; j++)
                    mma16816(acc[am][j], a[am], &b[j >> 1][(j & 1) * 2]);
        }
    }

    const int crow = lane >> 2, ccol = (lane & 3) * 2;
#pragma unroll
    for (int am = 0; am < 2; am++) {
#pragma unroll
        for (int j = 0; j < 8; j++) {
            int col = bn + wn + j * 8 + ccol;
            int r0  = bm + wm + am * 16 + crow;
            if (r0 < M) {
                *reinterpret_cast<float2*>(out + (size_t)r0 * OUTSTRIDE + col) =
                    make_float2(acc[am][j][0], acc[am][j][1]);
                *reinterpret_cast<__half2*>(g_ftH + (size_t)r0 * OUT_F + col) =
                    __floats2half2_rn(acc[am][j][0], acc[am][j][1]);
            }
            int r1 = r0 + 8;
            if (r1 < M) {
                *reinterpret_cast<float2*>(out + (size_t)r1 * OUTSTRIDE + col) =
                    make_float2(acc[am][j][2], acc[am][j][3]);
                *reinterpret_cast<__half2*>(g_ftH + (size_t)r1 * OUT_F + col) =
                    __floats2half2_rn(acc[am][j][2], acc[am][j][3]);
            }
        }
    }
}

// ---------------------------------------------------------------------------
// CSR scatter: one warp per dst node; gathers fp16 mirror (half traffic),
// accumulates fp32, ONE plain STG.128 per node. Unconditional write also
// zeroes empty dst nodes (no separate zero pass needed).
// ---------------------------------------------------------------------------
__global__ __launch_bounds__(256)
void scatter_csr_kernel(float* out, int M, int colOff) {
    const int d    = (blockIdx.x * blockDim.x + threadIdx.x) >> 5;  // dst node
    const int lane = threadIdx.x & 31;
    if (d >= M) return;

    const int end   = g_offs[d];
    const int start = end - g_hist[d];

    float4 acc = make_float4(0.f, 0.f, 0.f, 0.f);
    for (int base = start; base < end; base += 32) {
        const int n = min(32, end - base);
        int2 rec;
        if (lane < n) rec = __ldg(&g_pack[base + lane]);
        for (int j = 0; j < n; j++) {
            int   s = __shfl_sync(0xffffffffu, rec.x, j);
            float v = __int_as_float(__shfl_sync(0xffffffffu, rec.y, j));
            uint2 raw = __ldg(reinterpret_cast<const uint2*>(
                                  g_ftH + (size_t)s * OUT_F + colOff) + lane);
            float2 f0 = __half22float2(*reinterpret_cast<__half2*>(&raw.x));
            float2 f1 = __half22float2(*reinterpret_cast<__half2*>(&raw.y));
            acc.x += v * f0.x;
            acc.y += v * f0.y;
            acc.z += v * f1.x;
            acc.w += v * f1.y;
        }
    }
    *reinterpret_cast<float4*>(out + (size_t)d * OUTSTRIDE + OUT_F + colOff +
                               lane * 4) = acc;
}

// ---------------------------------------------------------------------------
extern "C" void kernel_launch(void* const* d_in, const int* in_sizes, int n_in,
                              void* d_out, int out_size) {
    const float* input  = (const float*)d_in[0];   // [N, 256]
    const void*  esrc   = d_in[1];
    const void*  edst   = d_in[2];
    const float* evals  = (const float*)d_in[3];
    const float* weight = (const float*)d_in[4];   // [256, 256]
    float* out = (float*)d_out;                    // [N, 512]

    const int M = in_sizes[0] / IN_F;              // 100000
    const int E = in_sizes[1];                     // 3200000

    static cudaStream_t s1 = nullptr, s2 = nullptr;
    static cudaEvent_t evRoot, ev1, evG0, ev2;
    if (!s1) {   // one-time resource creation (not memory allocation)
        cudaStreamCreateWithFlags(&s1, cudaStreamNonBlocking);
        cudaStreamCreateWithFlags(&s2, cudaStreamNonBlocking);
        cudaEventCreateWithFlags(&evRoot, cudaEventDisableTiming);
        cudaEventCreateWithFlags(&ev1,    cudaEventDisableTiming);
        cudaEventCreateWithFlags(&evG0,   cudaEventDisableTiming);
        cudaEventCreateWithFlags(&ev2,    cudaEventDisableTiming);
    }

    // ---- fork side stream s1 for the sort chain ----
    cudaEventRecord(evRoot, 0);
    cudaStreamWaitEvent(s1, evRoot, 0);

    // s1: counting sort (independent of GEMM)
    zero_hist_kernel<<<NB / 256, 256, 0, s1>>>();
    detect_idx_kernel<<<1, 256, 0, s1>>>((const unsigned*)esrc);
    hist_kernel<<<(E + 255) / 256, 256, 0, s1>>>(edst, E);
    scanA_kernel<<<NB / 256, 256, 0, s1>>>();
    scanB_kernel<<<1, 512, 0, s1>>>();
    scanC_kernel<<<NB / 256, 256, 0, s1>>>();
    sort_pack_kernel<<<(E + 255) / 256, 256, 0, s1>>>(esrc, edst, evals, E);
    cudaEventRecord(ev1, s1);

    // s0 (capture stream): convert W, GEMM half 0 (cols 0-127)
    conv_w_kernel<<<(IN_F * OUT_F) / 256, 256>>>(weight);
    dim3 gg((M + 127) / 128, 1);
    gemm_mma_kernel<<<gg, 256>>>(input, out, M, 0);
    cudaEventRecord(evG0, 0);

    // s2: GEMM half 1 (cols 128-255), overlaps scatter pass 0
    cudaStreamWaitEvent(s2, evG0, 0);
    gemm_mma_kernel<<<gg, 256, 0, s2>>>(input, out, M, 128);
    cudaEventRecord(ev2, s2);

    // s0: scatter pass 0 (needs sort chain + gemm half 0)
    cudaStreamWaitEvent(0, ev1, 0);
    scatter_csr_kernel<<<(M + 7) / 8, 256>>>(out, M, 0);

    // s0: scatter pass 1 (needs gemm half 1)
    cudaStreamWaitEvent(0, ev2, 0);
    scatter_csr_kernel<<<(M + 7) / 8, 256>>>(out, M, 128);
}